// round 1
// baseline (speedup 1.0000x reference)
#include <cuda_runtime.h>
#include <cuda_bf16.h>
#include <cstddef>

// ---------------------------------------------------------------------------
// Problem constants
// ---------------------------------------------------------------------------
#define BATCH   8
#define CH      64
#define NPTS    32768
#define RES     32
#define RCUBE   32768          // RES^3, coincidentally == NPTS
#define GRID_ELEMS (BATCH*CH*RCUBE)   // 16,777,216
#define LEAK    0.1f
#define NORM_EPS 1e-4f

// Output packing: (fused[B,C,N], coords[B,3,N], voxel_features[B,C,R,R,R])
#define OFF_FUSED   0
#define OFF_COORDS  (BATCH*CH*NPTS)                 // 16,777,216
#define OFF_VF      (OFF_COORDS + BATCH*3*NPTS)     // 17,563,648

// ---------------------------------------------------------------------------
// Scratch (device globals: allocation-free per harness rules)
// ---------------------------------------------------------------------------
__device__ float g_sums[GRID_ELEMS];        // scatter sums -> averaged grid (in place)
__device__ float g_cnt [BATCH*RCUBE];
__device__ float g_tmp [GRID_ELEMS];        // raw conv output
__device__ float g_h   [GRID_ELEMS];        // conv1 post-IN+leaky
__device__ float g_p   [GRID_ELEMS];        // point branch
__device__ float g_vft [GRID_ELEMS];        // voxel features transposed [b][vox][c]
__device__ float g_dv  [GRID_ELEMS];        // devoxelized [b][n][c]
__device__ float g_nc  [BATCH*3*NPTS];      // norm_coords
__device__ float g_mean[BATCH*3];
__device__ float g_denom[BATCH];

// ---------------------------------------------------------------------------
// 0. zero scratch
// ---------------------------------------------------------------------------
__global__ void zero_kernel() {
    int total = GRID_ELEMS + BATCH*RCUBE;
    for (int i = blockIdx.x*blockDim.x + threadIdx.x; i < total; i += gridDim.x*blockDim.x) {
        if (i < GRID_ELEMS) g_sums[i] = 0.f;
        else                g_cnt[i - GRID_ELEMS] = 0.f;
    }
}

// ---------------------------------------------------------------------------
// 1. per-batch coordinate mean
// ---------------------------------------------------------------------------
__global__ void mean_kernel(const float* __restrict__ coords) {
    int b = blockIdx.x, tid = threadIdx.x;
    const float* cb = coords + (size_t)b*3*NPTS;
    float s0 = 0.f, s1 = 0.f, s2 = 0.f;
    for (int n = tid; n < NPTS; n += 256) {
        s0 += cb[n]; s1 += cb[NPTS + n]; s2 += cb[2*NPTS + n];
    }
    for (int o = 16; o; o >>= 1) {
        s0 += __shfl_xor_sync(0xffffffffu, s0, o);
        s1 += __shfl_xor_sync(0xffffffffu, s1, o);
        s2 += __shfl_xor_sync(0xffffffffu, s2, o);
    }
    __shared__ float sh[3][8];
    int w = tid >> 5;
    if ((tid & 31) == 0) { sh[0][w] = s0; sh[1][w] = s1; sh[2][w] = s2; }
    __syncthreads();
    if (tid == 0) {
        float t0 = 0.f, t1 = 0.f, t2 = 0.f;
        for (int i = 0; i < 8; i++) { t0 += sh[0][i]; t1 += sh[1][i]; t2 += sh[2][i]; }
        g_mean[b*3+0] = t0 / (float)NPTS;
        g_mean[b*3+1] = t1 / (float)NPTS;
        g_mean[b*3+2] = t2 / (float)NPTS;
    }
}

// ---------------------------------------------------------------------------
// 2. per-batch max point norm -> denom = 2*max||c||
// ---------------------------------------------------------------------------
__global__ void maxnorm_kernel(const float* __restrict__ coords) {
    int b = blockIdx.x, tid = threadIdx.x;
    const float* cb = coords + (size_t)b*3*NPTS;
    float m0 = g_mean[b*3+0], m1 = g_mean[b*3+1], m2 = g_mean[b*3+2];
    float mx = 0.f;
    for (int n = tid; n < NPTS; n += 256) {
        float dx = cb[n] - m0, dy = cb[NPTS+n] - m1, dz = cb[2*NPTS+n] - m2;
        float sq = dx*dx + dy*dy + dz*dz;
        mx = fmaxf(mx, sq);
    }
    for (int o = 16; o; o >>= 1) mx = fmaxf(mx, __shfl_xor_sync(0xffffffffu, mx, o));
    __shared__ float sh[8];
    int w = tid >> 5;
    if ((tid & 31) == 0) sh[w] = mx;
    __syncthreads();
    if (tid == 0) {
        float t = 0.f;
        for (int i = 0; i < 8; i++) t = fmaxf(t, sh[i]);
        g_denom[b] = 2.0f * sqrtf(t);
    }
}

// ---------------------------------------------------------------------------
// 3. compute norm_coords, voxel idx, scatter-add counts + features
// ---------------------------------------------------------------------------
__global__ void voxscatter_kernel(const float* __restrict__ coords,
                                  const float* __restrict__ features) {
    int t = blockIdx.x*blockDim.x + threadIdx.x;   // BATCH*NPTS threads
    int b = t >> 15, n = t & (NPTS-1);
    float den = g_denom[b];
    int vi[3];
#pragma unroll
    for (int d = 0; d < 3; d++) {
        float c = coords[((size_t)b*3 + d)*NPTS + n];
        float v = (c - g_mean[b*3+d]) / den + 0.5f;   // IEEE div, matches ref
        v *= (float)RES;
        v = fminf(fmaxf(v, 0.f), (float)(RES-1));
        g_nc[((size_t)b*3 + d)*NPTS + n] = v;
        vi[d] = (int)rintf(v);                        // round-half-even == jnp.round
    }
    int vox = vi[0]*RES*RES + vi[1]*RES + vi[2];
    atomicAdd(&g_cnt[b*RCUBE + vox], 1.f);
    size_t fb = (size_t)b*CH*NPTS + n;
    size_t sb = (size_t)b*CH*RCUBE + vox;
#pragma unroll 4
    for (int c = 0; c < CH; c++)
        atomicAdd(&g_sums[sb + (size_t)c*RCUBE], features[fb + (size_t)c*NPTS]);
}

// ---------------------------------------------------------------------------
// 4. average (in place over g_sums)
// ---------------------------------------------------------------------------
__global__ void avg_kernel() {
    for (int i = blockIdx.x*blockDim.x + threadIdx.x; i < GRID_ELEMS; i += gridDim.x*blockDim.x) {
        int b   = i >> 21;            // CH*RCUBE = 2^21
        int vox = i & (RCUBE-1);
        g_sums[i] = g_sums[i] / fmaxf(g_cnt[b*RCUBE + vox], 1.f);
    }
}

// ---------------------------------------------------------------------------
// 5. Conv3d 3x3x3, SAME zero pad.  in/out: [B][64][32][32][32] (d,h,w; w fastest)
//    Block = (b, d, h-half).  512 threads = 8 co-groups x 16 h x 4 w-octets.
//    Thread accumulates 8(co) x 8(w).  Smem: 8-ci input slab + weights.
// ---------------------------------------------------------------------------
#define CI_CHUNK 8
#define SIN_FLOATS (CI_CHUNK*3*18*35)         // 15120 (stride-35 pad: conflict-free)
#define SW_FLOATS  (CI_CHUNK*27*64)           // 13824
#define CONV_SMEM_BYTES ((SIN_FLOATS + SW_FLOATS)*4)

__global__ __launch_bounds__(512, 1)
void conv3d_kernel(const float* __restrict__ in, const float* __restrict__ W,
                   const float* __restrict__ bias, float* __restrict__ out) {
    extern __shared__ float smem[];
    float (*sIn)[3][18][35] = (float (*)[3][18][35])smem;
    float (*sW)[27][64]     = (float (*)[27][64])(smem + SIN_FLOATS);

    int bid = blockIdx.x;
    int hh = bid & 1, d = (bid >> 1) & 31, b = bid >> 6;
    int h0 = hh * 16;
    int tid = threadIdx.x;
    int cg = tid >> 6;            // 0..7 -> co0 = cg*8 (uniform per warp)
    int r  = tid & 63;
    int hl = r >> 2;              // 0..15
    int wg = r & 3;               // 0..3 -> wbase = wg*8
    int co0 = cg * 8;
    int wbase = wg * 8;

    float acc[8][8];
#pragma unroll
    for (int j = 0; j < 8; j++)
#pragma unroll
        for (int i = 0; i < 8; i++) acc[j][i] = 0.f;

    const float* inB = in + (size_t)b*CH*RCUBE;

    for (int ci0 = 0; ci0 < CH; ci0 += CI_CHUNK) {
        // input slab: ci x 3(d) x 18(h halo) x 34(w halo), zero-padded
        for (int t = tid; t < CI_CHUNK*3*18*34; t += 512) {
            int ww = t % 34;
            int rest = t / 34;
            int hy = rest % 18; rest /= 18;
            int dd = rest % 3;
            int ci = rest / 3;
            int gd = d - 1 + dd;
            int gh = h0 - 1 + hy;
            int gw = ww - 1;
            float v = 0.f;
            if ((unsigned)gd < 32u && (unsigned)gh < 32u && (unsigned)gw < 32u)
                v = inB[(size_t)(ci0+ci)*RCUBE + gd*1024 + gh*32 + gw];
            sIn[ci][dd][hy][ww] = v;
        }
        // weights: sW[ci][k][co] from W[co][ci][k]
        for (int t = tid; t < CI_CHUNK*27*64; t += 512) {
            int co = t & 63;
            int rest = t >> 6;
            int k = rest % 27;
            int ci = rest / 27;
            sW[ci][k][co] = W[((size_t)co*CH + ci0 + ci)*27 + k];
        }
        __syncthreads();

#pragma unroll 1
        for (int ci = 0; ci < CI_CHUNK; ci++) {
#pragma unroll 1
            for (int dd = 0; dd < 3; dd++) {
#pragma unroll
                for (int dh = 0; dh < 3; dh++) {
                    float inv[10];
#pragma unroll
                    for (int i = 0; i < 10; i++) inv[i] = sIn[ci][dd][hl+dh][wbase+i];
#pragma unroll
                    for (int dw = 0; dw < 3; dw++) {
                        int k = (dd*3 + dh)*3 + dw;
#pragma unroll
                        for (int j = 0; j < 8; j++) {
                            float wv = sW[ci][k][co0+j];
#pragma unroll
                            for (int i = 0; i < 8; i++)
                                acc[j][i] = fmaf(wv, inv[i+dw], acc[j][i]);
                        }
                    }
                }
            }
        }
        __syncthreads();
    }

    int h = h0 + hl;
#pragma unroll
    for (int j = 0; j < 8; j++) {
        float bb = bias[co0+j];
        size_t ob = ((size_t)b*CH + co0 + j)*RCUBE + d*1024 + h*32 + wbase;
#pragma unroll
        for (int i = 0; i < 8; i++) out[ob + i] = acc[j][i] + bb;
    }
}

// ---------------------------------------------------------------------------
// 6. InstanceNorm (+LeakyReLU) over M=32768 per (b,c) group. 512 blocks.
// ---------------------------------------------------------------------------
__global__ void instnorm_kernel(const float* __restrict__ in, float* __restrict__ out) {
    int g = blockIdx.x, tid = threadIdx.x;
    const float* x = in + (size_t)g*RCUBE;
    float s = 0.f, s2 = 0.f;
    for (int i = tid; i < RCUBE; i += 256) {
        float v = x[i];
        s += v;
        s2 = fmaf(v, v, s2);
    }
    for (int o = 16; o; o >>= 1) {
        s  += __shfl_xor_sync(0xffffffffu, s,  o);
        s2 += __shfl_xor_sync(0xffffffffu, s2, o);
    }
    __shared__ float shs[8], shs2[8];
    __shared__ float smean, srstd;
    int w = tid >> 5;
    if ((tid & 31) == 0) { shs[w] = s; shs2[w] = s2; }
    __syncthreads();
    if (tid == 0) {
        float a = 0.f, b2 = 0.f;
        for (int i = 0; i < 8; i++) { a += shs[i]; b2 += shs2[i]; }
        float m   = a / (float)RCUBE;
        float var = fmaxf(b2 / (float)RCUBE - m*m, 0.f);
        smean = m;
        srstd = rsqrtf(var + NORM_EPS);
    }
    __syncthreads();
    float m = smean, rs = srstd;
    float* y = out + (size_t)g*RCUBE;
    for (int i = tid; i < RCUBE; i += 256) {
        float v = (x[i] - m) * rs;
        y[i] = (v >= 0.f) ? v : LEAK * v;
    }
}

// ---------------------------------------------------------------------------
// 7. transpose voxel features [b][c][vox] -> g_vft[b][vox][c]
// ---------------------------------------------------------------------------
__global__ void transpose_kernel(const float* __restrict__ vf) {
    __shared__ float t[32][33];
    int b = blockIdx.z, ct = blockIdx.y, vt = blockIdx.x;
    int tx = threadIdx.x & 31, ty = threadIdx.x >> 5;    // 32x8
    const float* src = vf + ((size_t)b*CH + ct*32)*RCUBE + vt*32;
#pragma unroll
    for (int k = 0; k < 32; k += 8) t[ty+k][tx] = src[(size_t)(ty+k)*RCUBE + tx];
    __syncthreads();
    float* dst = g_vft + ((size_t)b*RCUBE + vt*32)*CH + ct*32;
#pragma unroll
    for (int k = 0; k < 32; k += 8) dst[(size_t)(ty+k)*CH + tx] = t[tx][ty+k];
}

// ---------------------------------------------------------------------------
// 8. point branch: p[b][o][n] = sum_c pw[o][c]*f[b][c][n] + pb[o]
// ---------------------------------------------------------------------------
__global__ void pointmlp_kernel(const float* __restrict__ features,
                                const float* __restrict__ pw,
                                const float* __restrict__ pb) {
    __shared__ float sw[64*64];
    __shared__ float sb[64];
    int tid = threadIdx.x;
    for (int i = tid; i < 4096; i += 256) sw[i] = pw[i];
    if (tid < 64) sb[tid] = pb[tid];
    __syncthreads();
    int blk = blockIdx.x;
    int b = blk >> 7;
    int n = (blk & 127)*256 + tid;
    float acc[64];
#pragma unroll
    for (int o = 0; o < 64; o++) acc[o] = 0.f;
    const float* f = features + (size_t)b*CH*NPTS + n;
    for (int c = 0; c < 64; c++) {
        float v = f[(size_t)c*NPTS];
#pragma unroll
        for (int o = 0; o < 64; o++) acc[o] = fmaf(sw[o*64 + c], v, acc[o]);
    }
    float* p = g_p + (size_t)b*CH*NPTS + n;
#pragma unroll
    for (int o = 0; o < 64; o++) p[(size_t)o*NPTS] = acc[o] + sb[o];
}

// ---------------------------------------------------------------------------
// 9. trilinear devoxelize: warp per point, lanes over channels -> g_dv[b][n][c]
// ---------------------------------------------------------------------------
__global__ void devox_kernel() {
    int tid = threadIdx.x;
    int warp = tid >> 5, lane = tid & 31;
    int pidx = blockIdx.x*8 + warp;           // over BATCH*NPTS
    int b = pidx >> 15, n = pidx & (NPTS-1);
    float nx = g_nc[((size_t)b*3 + 0)*NPTS + n];
    float ny = g_nc[((size_t)b*3 + 1)*NPTS + n];
    float nz = g_nc[((size_t)b*3 + 2)*NPTS + n];
    int lx = (int)floorf(nx), ly = (int)floorf(ny), lz = (int)floorf(nz);
    float fx = nx - (float)lx, fy = ny - (float)ly, fz = nz - (float)lz;
    int hx = min(lx+1, 31), hy = min(ly+1, 31), hz = min(lz+1, 31);
    const float* base = g_vft + (size_t)b*RCUBE*CH;
    float a0 = 0.f, a1 = 0.f;
#pragma unroll
    for (int k = 0; k < 8; k++) {
        int dx = k >> 2, dy = (k >> 1) & 1, dz = k & 1;
        int ix = dx ? hx : lx, iy = dy ? hy : ly, iz = dz ? hz : lz;
        float wgt = (dx ? fx : 1.f-fx) * (dy ? fy : 1.f-fy) * (dz ? fz : 1.f-fz);
        const float* p = base + (size_t)(ix*1024 + iy*32 + iz)*CH;
        a0 = fmaf(wgt, p[lane],      a0);
        a1 = fmaf(wgt, p[lane + 32], a1);
    }
    float* d = g_dv + ((size_t)b*NPTS + n)*CH;
    d[lane]      = a0;
    d[lane + 32] = a1;
}

// ---------------------------------------------------------------------------
// 10. final: fused[b][c][n] = dv[b][n][c] (transposed via smem) + p_norm[b][c][n]
// ---------------------------------------------------------------------------
__global__ void final_kernel(const float* __restrict__ pn, float* __restrict__ outf) {
    __shared__ float t[32][65];
    int blk = blockIdx.x;
    int b = blk >> 10;
    int n0 = (blk & 1023)*32;
    int tid = threadIdx.x;
    const float* dvb = g_dv + ((size_t)b*NPTS + n0)*CH;
    for (int i = tid; i < 2048; i += 256) {
        int c = i & 63, nl = i >> 6;
        t[nl][c] = dvb[(size_t)nl*CH + c];
    }
    __syncthreads();
    size_t ob = (size_t)b*CH*NPTS + n0;
    for (int i = tid; i < 2048; i += 256) {
        int nl = i & 31, c = i >> 5;
        size_t o = ob + (size_t)c*NPTS + nl;
        outf[o] = t[nl][c] + pn[o];
    }
}

// ---------------------------------------------------------------------------
// launch
// ---------------------------------------------------------------------------
extern "C" void kernel_launch(void* const* d_in, const int* in_sizes, int n_in,
                              void* d_out, int out_size) {
    const float* features = (const float*)d_in[0];
    const float* coords   = (const float*)d_in[1];
    const float* c1w      = (const float*)d_in[2];
    const float* c1b      = (const float*)d_in[3];
    const float* c2w      = (const float*)d_in[4];
    const float* c2b      = (const float*)d_in[5];
    const float* pw       = (const float*)d_in[6];
    const float* pb       = (const float*)d_in[7];
    float* out = (float*)d_out;
    float* out_fused  = out + OFF_FUSED;
    float* out_coords = out + OFF_COORDS;
    float* out_vf     = out + OFF_VF;

    float *p_sums, *p_tmp, *p_h, *p_p;
    cudaGetSymbolAddress((void**)&p_sums, g_sums);
    cudaGetSymbolAddress((void**)&p_tmp,  g_tmp);
    cudaGetSymbolAddress((void**)&p_h,    g_h);
    cudaGetSymbolAddress((void**)&p_p,    g_p);

    cudaFuncSetAttribute(conv3d_kernel,
                         cudaFuncAttributeMaxDynamicSharedMemorySize, CONV_SMEM_BYTES);

    zero_kernel<<<8192, 256>>>();
    mean_kernel<<<BATCH, 256>>>(coords);
    maxnorm_kernel<<<BATCH, 256>>>(coords);
    voxscatter_kernel<<<BATCH*NPTS/256, 256>>>(coords, features);
    avg_kernel<<<8192, 256>>>();

    conv3d_kernel<<<BATCH*32*2, 512, CONV_SMEM_BYTES>>>(p_sums, c1w, c1b, p_tmp);
    instnorm_kernel<<<BATCH*CH, 256>>>(p_tmp, p_h);
    conv3d_kernel<<<BATCH*32*2, 512, CONV_SMEM_BYTES>>>(p_h, c2w, c2b, p_tmp);
    instnorm_kernel<<<BATCH*CH, 256>>>(p_tmp, out_vf);

    transpose_kernel<<<dim3(1024, 2, BATCH), 256>>>(out_vf);

    pointmlp_kernel<<<BATCH*128, 256>>>(features, pw, pb);
    instnorm_kernel<<<BATCH*CH, 256>>>(p_p, p_p);

    devox_kernel<<<BATCH*NPTS/8, 256>>>();
    final_kernel<<<BATCH*1024, 256>>>(p_p, out_fused);

    cudaMemcpyAsync(out_coords, coords, (size_t)BATCH*3*NPTS*sizeof(float),
                    cudaMemcpyDeviceToDevice);
}

// round 2
// speedup vs baseline: 1.0769x; 1.0769x over previous
#include <cuda_runtime.h>
#include <cuda_bf16.h>
#include <cstddef>

// ---------------------------------------------------------------------------
// Problem constants
// ---------------------------------------------------------------------------
#define BATCH   8
#define CH      64
#define NPTS    32768
#define RES     32
#define RCUBE   32768
#define GRID_ELEMS (BATCH*CH*RCUBE)   // 16,777,216
#define LEAK    0.1f
#define NORM_EPS 1e-4f

#define OFF_FUSED   0
#define OFF_COORDS  (BATCH*CH*NPTS)
#define OFF_VF      (OFF_COORDS + BATCH*3*NPTS)

typedef unsigned long long ull;

// ---------------------------------------------------------------------------
// Scratch
// ---------------------------------------------------------------------------
__device__ float g_sums[GRID_ELEMS];
__device__ float g_cnt [BATCH*RCUBE];
__device__ float g_tmp [GRID_ELEMS];
__device__ float g_h   [GRID_ELEMS];
__device__ float g_p   [GRID_ELEMS];
__device__ float g_vft [GRID_ELEMS];
__device__ float g_dv  [GRID_ELEMS];
__device__ float g_nc  [BATCH*3*NPTS];
__device__ float g_mean[BATCH*3];
__device__ float g_denom[BATCH];
// per-(b,c) conv-output stats (sum, sumsq), one set per conv
__device__ float g_st1s[BATCH*CH];
__device__ float g_st1q[BATCH*CH];
__device__ float g_st2s[BATCH*CH];
__device__ float g_st2q[BATCH*CH];

// ---------------------------------------------------------------------------
// packed fp32x2 helpers (full-rate FMA path on Blackwell)
// ---------------------------------------------------------------------------
__device__ __forceinline__ ull fma2(ull a, ull b, ull c) {
    ull d;
    asm("fma.rn.f32x2 %0, %1, %2, %3;" : "=l"(d) : "l"(a), "l"(b), "l"(c));
    return d;
}
__device__ __forceinline__ ull dup2(float v) {
    ull d;
    asm("mov.b64 %0, {%1, %1};" : "=l"(d) : "f"(v));
    return d;
}
__device__ __forceinline__ void unpack2(ull v, float& lo, float& hi) {
    asm("mov.b64 {%0, %1}, %2;" : "=f"(lo), "=f"(hi) : "l"(v));
}

// ---------------------------------------------------------------------------
// 0. zero scratch (sums, counts, stats)
// ---------------------------------------------------------------------------
__global__ void zero_kernel() {
    int total = GRID_ELEMS + BATCH*RCUBE;
    for (int i = blockIdx.x*blockDim.x + threadIdx.x; i < total; i += gridDim.x*blockDim.x) {
        if (i < GRID_ELEMS) g_sums[i] = 0.f;
        else                g_cnt[i - GRID_ELEMS] = 0.f;
    }
    int t = blockIdx.x*blockDim.x + threadIdx.x;
    if (t < BATCH*CH) {
        g_st1s[t] = 0.f; g_st1q[t] = 0.f;
        g_st2s[t] = 0.f; g_st2q[t] = 0.f;
    }
}

// ---------------------------------------------------------------------------
// 1. per-batch coordinate mean
// ---------------------------------------------------------------------------
__global__ void mean_kernel(const float* __restrict__ coords) {
    int b = blockIdx.x, tid = threadIdx.x;
    const float* cb = coords + (size_t)b*3*NPTS;
    float s0 = 0.f, s1 = 0.f, s2 = 0.f;
    for (int n = tid; n < NPTS; n += 256) {
        s0 += cb[n]; s1 += cb[NPTS + n]; s2 += cb[2*NPTS + n];
    }
    for (int o = 16; o; o >>= 1) {
        s0 += __shfl_xor_sync(0xffffffffu, s0, o);
        s1 += __shfl_xor_sync(0xffffffffu, s1, o);
        s2 += __shfl_xor_sync(0xffffffffu, s2, o);
    }
    __shared__ float sh[3][8];
    int w = tid >> 5;
    if ((tid & 31) == 0) { sh[0][w] = s0; sh[1][w] = s1; sh[2][w] = s2; }
    __syncthreads();
    if (tid == 0) {
        float t0 = 0.f, t1 = 0.f, t2 = 0.f;
        for (int i = 0; i < 8; i++) { t0 += sh[0][i]; t1 += sh[1][i]; t2 += sh[2][i]; }
        g_mean[b*3+0] = t0 / (float)NPTS;
        g_mean[b*3+1] = t1 / (float)NPTS;
        g_mean[b*3+2] = t2 / (float)NPTS;
    }
}

// ---------------------------------------------------------------------------
// 2. per-batch max point norm
// ---------------------------------------------------------------------------
__global__ void maxnorm_kernel(const float* __restrict__ coords) {
    int b = blockIdx.x, tid = threadIdx.x;
    const float* cb = coords + (size_t)b*3*NPTS;
    float m0 = g_mean[b*3+0], m1 = g_mean[b*3+1], m2 = g_mean[b*3+2];
    float mx = 0.f;
    for (int n = tid; n < NPTS; n += 256) {
        float dx = cb[n] - m0, dy = cb[NPTS+n] - m1, dz = cb[2*NPTS+n] - m2;
        float sq = dx*dx + dy*dy + dz*dz;
        mx = fmaxf(mx, sq);
    }
    for (int o = 16; o; o >>= 1) mx = fmaxf(mx, __shfl_xor_sync(0xffffffffu, mx, o));
    __shared__ float sh[8];
    int w = tid >> 5;
    if ((tid & 31) == 0) sh[w] = mx;
    __syncthreads();
    if (tid == 0) {
        float t = 0.f;
        for (int i = 0; i < 8; i++) t = fmaxf(t, sh[i]);
        g_denom[b] = 2.0f * sqrtf(t);
    }
}

// ---------------------------------------------------------------------------
// 3. norm_coords + scatter-add
// ---------------------------------------------------------------------------
__global__ void voxscatter_kernel(const float* __restrict__ coords,
                                  const float* __restrict__ features) {
    int t = blockIdx.x*blockDim.x + threadIdx.x;
    int b = t >> 15, n = t & (NPTS-1);
    float den = g_denom[b];
    int vi[3];
#pragma unroll
    for (int d = 0; d < 3; d++) {
        float c = coords[((size_t)b*3 + d)*NPTS + n];
        float v = (c - g_mean[b*3+d]) / den + 0.5f;
        v *= (float)RES;
        v = fminf(fmaxf(v, 0.f), (float)(RES-1));
        g_nc[((size_t)b*3 + d)*NPTS + n] = v;
        vi[d] = (int)rintf(v);
    }
    int vox = vi[0]*RES*RES + vi[1]*RES + vi[2];
    atomicAdd(&g_cnt[b*RCUBE + vox], 1.f);
    size_t fb = (size_t)b*CH*NPTS + n;
    size_t sb = (size_t)b*CH*RCUBE + vox;
#pragma unroll 4
    for (int c = 0; c < CH; c++)
        atomicAdd(&g_sums[sb + (size_t)c*RCUBE], features[fb + (size_t)c*NPTS]);
}

// ---------------------------------------------------------------------------
// 4. average
// ---------------------------------------------------------------------------
__global__ void avg_kernel() {
    for (int i = blockIdx.x*blockDim.x + threadIdx.x; i < GRID_ELEMS; i += gridDim.x*blockDim.x) {
        int b   = i >> 21;
        int vox = i & (RCUBE-1);
        g_sums[i] = g_sums[i] / fmaxf(g_cnt[b*RCUBE + vox], 1.f);
    }
}

// ---------------------------------------------------------------------------
// 5. Conv3d 3x3x3 SAME, packed f32x2 core, fused IN-stat accumulation.
//    Block=(b,d,h-half). 512 thr = 8 co-groups x 16 h x 4 w-octets.
//    Thread tile: 8(co) x 8(w) held as 4 co-pairs x 8 w of f32x2.
// ---------------------------------------------------------------------------
#define CI_CHUNK 8
#define SIN_FLOATS (CI_CHUNK*3*18*35)         // 15120 (35-stride: conflict-free, 8B-aligned)
#define SW_FLOATS  (CI_CHUNK*27*64)           // 13824
#define CONV_SMEM_BYTES ((SIN_FLOATS + SW_FLOATS)*4)

__global__ __launch_bounds__(512, 1)
void conv3d_kernel(const float* __restrict__ in, const float* __restrict__ W,
                   const float* __restrict__ bias, float* __restrict__ out,
                   float* __restrict__ stat_s, float* __restrict__ stat_q) {
    extern __shared__ float smem[];
    float (*sIn)[3][18][35] = (float (*)[3][18][35])smem;
    float (*sW)[27][64]     = (float (*)[27][64])(smem + SIN_FLOATS);

    int bid = blockIdx.x;
    int hh = bid & 1, d = (bid >> 1) & 31, b = bid >> 6;
    int h0 = hh * 16;
    int tid = threadIdx.x;
    int cg = tid >> 6;            // uniform per warp
    int r  = tid & 63;
    int hl = r >> 2;
    int wg = r & 3;
    int co0 = cg * 8;
    int wbase = wg * 8;

    ull acc2[4][8];               // [co-pair][w]
#pragma unroll
    for (int jp = 0; jp < 4; jp++)
#pragma unroll
        for (int i = 0; i < 8; i++) acc2[jp][i] = 0ull;

    const float* inB = in + (size_t)b*CH*RCUBE;

    for (int ci0 = 0; ci0 < CH; ci0 += CI_CHUNK) {
        for (int t = tid; t < CI_CHUNK*3*18*34; t += 512) {
            int ww = t % 34;
            int rest = t / 34;
            int hy = rest % 18; rest /= 18;
            int dd = rest % 3;
            int ci = rest / 3;
            int gd = d - 1 + dd;
            int gh = h0 - 1 + hy;
            int gw = ww - 1;
            float v = 0.f;
            if ((unsigned)gd < 32u && (unsigned)gh < 32u && (unsigned)gw < 32u)
                v = inB[(size_t)(ci0+ci)*RCUBE + gd*1024 + gh*32 + gw];
            sIn[ci][dd][hy][ww] = v;
        }
        for (int t = tid; t < CI_CHUNK*27*64; t += 512) {
            int co = t & 63;
            int rest = t >> 6;
            int k = rest % 27;
            int ci = rest / 27;
            sW[ci][k][co] = W[((size_t)co*CH + ci0 + ci)*27 + k];
        }
        __syncthreads();

#pragma unroll 1
        for (int ci = 0; ci < CI_CHUNK; ci++) {
#pragma unroll 1
            for (int dd = 0; dd < 3; dd++) {
#pragma unroll 1
                for (int dh = 0; dh < 3; dh++) {
                    ull invd[10];
#pragma unroll
                    for (int i = 0; i < 10; i++)
                        invd[i] = dup2(sIn[ci][dd][hl+dh][wbase+i]);
#pragma unroll
                    for (int dw = 0; dw < 3; dw++) {
                        int k = (dd*3 + dh)*3 + dw;
                        const ull* wp = (const ull*)&sW[ci][k][co0];
#pragma unroll
                        for (int jp = 0; jp < 4; jp++) {
                            ull w2 = wp[jp];                  // broadcast LDS.64
#pragma unroll
                            for (int i = 0; i < 8; i++)
                                acc2[jp][i] = fma2(w2, invd[i+dw], acc2[jp][i]);
                        }
                    }
                }
            }
        }
        __syncthreads();
    }

    // epilogue: unpack per-co, add bias, store, accumulate IN stats
    int h = h0 + hl;
#pragma unroll
    for (int j = 0; j < 8; j++) {
        int co = co0 + j;
        float bb = bias[co];
        size_t ob = ((size_t)b*CH + co)*RCUBE + d*1024 + h*32 + wbase;
        float s = 0.f, q = 0.f;
#pragma unroll
        for (int i = 0; i < 8; i++) {
            float lo, hi;
            unpack2(acc2[j >> 1][i], lo, hi);
            float v = ((j & 1) ? hi : lo) + bb;
            out[ob + i] = v;
            s += v;
            q = fmaf(v, v, q);
        }
        // warp-reduce (all lanes of this warp share co)
        for (int o = 16; o; o >>= 1) {
            s += __shfl_xor_sync(0xffffffffu, s, o);
            q += __shfl_xor_sync(0xffffffffu, q, o);
        }
        if ((tid & 31) == 0) {
            atomicAdd(&stat_s[b*CH + co], s);
            atomicAdd(&stat_q[b*CH + co], q);
        }
    }
}

// ---------------------------------------------------------------------------
// 6a. InstanceNorm apply (+leaky) from precomputed stats — single pass
// ---------------------------------------------------------------------------
__global__ void instnorm_apply_kernel(const float* __restrict__ in, float* __restrict__ out,
                                      const float* __restrict__ ss, const float* __restrict__ sq) {
    int g = blockIdx.x, tid = threadIdx.x;
    float m   = ss[g] / (float)RCUBE;
    float var = fmaxf(sq[g] / (float)RCUBE - m*m, 0.f);
    float rs  = rsqrtf(var + NORM_EPS);
    const float* x = in + (size_t)g*RCUBE;
    float* y = out + (size_t)g*RCUBE;
    for (int i = tid; i < RCUBE; i += 256) {
        float v = (x[i] - m) * rs;
        y[i] = (v >= 0.f) ? v : LEAK * v;
    }
}

// ---------------------------------------------------------------------------
// 6b. full InstanceNorm (+leaky) — point branch
// ---------------------------------------------------------------------------
__global__ void instnorm_kernel(const float* __restrict__ in, float* __restrict__ out) {
    int g = blockIdx.x, tid = threadIdx.x;
    const float* x = in + (size_t)g*RCUBE;
    float s = 0.f, s2 = 0.f;
    for (int i = tid; i < RCUBE; i += 256) {
        float v = x[i];
        s += v;
        s2 = fmaf(v, v, s2);
    }
    for (int o = 16; o; o >>= 1) {
        s  += __shfl_xor_sync(0xffffffffu, s,  o);
        s2 += __shfl_xor_sync(0xffffffffu, s2, o);
    }
    __shared__ float shs[8], shs2[8];
    __shared__ float smean, srstd;
    int w = tid >> 5;
    if ((tid & 31) == 0) { shs[w] = s; shs2[w] = s2; }
    __syncthreads();
    if (tid == 0) {
        float a = 0.f, b2 = 0.f;
        for (int i = 0; i < 8; i++) { a += shs[i]; b2 += shs2[i]; }
        float m   = a / (float)RCUBE;
        float var = fmaxf(b2 / (float)RCUBE - m*m, 0.f);
        smean = m;
        srstd = rsqrtf(var + NORM_EPS);
    }
    __syncthreads();
    float m = smean, rs = srstd;
    float* y = out + (size_t)g*RCUBE;
    for (int i = tid; i < RCUBE; i += 256) {
        float v = (x[i] - m) * rs;
        y[i] = (v >= 0.f) ? v : LEAK * v;
    }
}

// ---------------------------------------------------------------------------
// 7. transpose voxel features [b][c][vox] -> [b][vox][c]
// ---------------------------------------------------------------------------
__global__ void transpose_kernel(const float* __restrict__ vf) {
    __shared__ float t[32][33];
    int b = blockIdx.z, ct = blockIdx.y, vt = blockIdx.x;
    int tx = threadIdx.x & 31, ty = threadIdx.x >> 5;
    const float* src = vf + ((size_t)b*CH + ct*32)*RCUBE + vt*32;
#pragma unroll
    for (int k = 0; k < 32; k += 8) t[ty+k][tx] = src[(size_t)(ty+k)*RCUBE + tx];
    __syncthreads();
    float* dst = g_vft + ((size_t)b*RCUBE + vt*32)*CH + ct*32;
#pragma unroll
    for (int k = 0; k < 32; k += 8) dst[(size_t)(ty+k)*CH + tx] = t[tx][ty+k];
}

// ---------------------------------------------------------------------------
// 8. point branch GEMM
// ---------------------------------------------------------------------------
__global__ void pointmlp_kernel(const float* __restrict__ features,
                                const float* __restrict__ pw,
                                const float* __restrict__ pb) {
    __shared__ float sw[64*64];
    __shared__ float sb[64];
    int tid = threadIdx.x;
    for (int i = tid; i < 4096; i += 256) sw[i] = pw[i];
    if (tid < 64) sb[tid] = pb[tid];
    __syncthreads();
    int blk = blockIdx.x;
    int b = blk >> 7;
    int n = (blk & 127)*256 + tid;
    float acc[64];
#pragma unroll
    for (int o = 0; o < 64; o++) acc[o] = 0.f;
    const float* f = features + (size_t)b*CH*NPTS + n;
    for (int c = 0; c < 64; c++) {
        float v = f[(size_t)c*NPTS];
#pragma unroll
        for (int o = 0; o < 64; o++) acc[o] = fmaf(sw[o*64 + c], v, acc[o]);
    }
    float* p = g_p + (size_t)b*CH*NPTS + n;
#pragma unroll
    for (int o = 0; o < 64; o++) p[(size_t)o*NPTS] = acc[o] + sb[o];
}

// ---------------------------------------------------------------------------
// 9. trilinear devoxelize
// ---------------------------------------------------------------------------
__global__ void devox_kernel() {
    int tid = threadIdx.x;
    int warp = tid >> 5, lane = tid & 31;
    int pidx = blockIdx.x*8 + warp;
    int b = pidx >> 15, n = pidx & (NPTS-1);
    float nx = g_nc[((size_t)b*3 + 0)*NPTS + n];
    float ny = g_nc[((size_t)b*3 + 1)*NPTS + n];
    float nz = g_nc[((size_t)b*3 + 2)*NPTS + n];
    int lx = (int)floorf(nx), ly = (int)floorf(ny), lz = (int)floorf(nz);
    float fx = nx - (float)lx, fy = ny - (float)ly, fz = nz - (float)lz;
    int hx = min(lx+1, 31), hy = min(ly+1, 31), hz = min(lz+1, 31);
    const float* base = g_vft + (size_t)b*RCUBE*CH;
    float a0 = 0.f, a1 = 0.f;
#pragma unroll
    for (int k = 0; k < 8; k++) {
        int dx = k >> 2, dy = (k >> 1) & 1, dz = k & 1;
        int ix = dx ? hx : lx, iy = dy ? hy : ly, iz = dz ? hz : lz;
        float wgt = (dx ? fx : 1.f-fx) * (dy ? fy : 1.f-fy) * (dz ? fz : 1.f-fz);
        const float* p = base + (size_t)(ix*1024 + iy*32 + iz)*CH;
        a0 = fmaf(wgt, p[lane],      a0);
        a1 = fmaf(wgt, p[lane + 32], a1);
    }
    float* d = g_dv + ((size_t)b*NPTS + n)*CH;
    d[lane]      = a0;
    d[lane + 32] = a1;
}

// ---------------------------------------------------------------------------
// 10. final fuse
// ---------------------------------------------------------------------------
__global__ void final_kernel(const float* __restrict__ pn, float* __restrict__ outf) {
    __shared__ float t[32][65];
    int blk = blockIdx.x;
    int b = blk >> 10;
    int n0 = (blk & 1023)*32;
    int tid = threadIdx.x;
    const float* dvb = g_dv + ((size_t)b*NPTS + n0)*CH;
    for (int i = tid; i < 2048; i += 256) {
        int c = i & 63, nl = i >> 6;
        t[nl][c] = dvb[(size_t)nl*CH + c];
    }
    __syncthreads();
    size_t ob = (size_t)b*CH*NPTS + n0;
    for (int i = tid; i < 2048; i += 256) {
        int nl = i & 31, c = i >> 5;
        size_t o = ob + (size_t)c*NPTS + nl;
        outf[o] = t[nl][c] + pn[o];
    }
}

// ---------------------------------------------------------------------------
// launch
// ---------------------------------------------------------------------------
extern "C" void kernel_launch(void* const* d_in, const int* in_sizes, int n_in,
                              void* d_out, int out_size) {
    const float* features = (const float*)d_in[0];
    const float* coords   = (const float*)d_in[1];
    const float* c1w      = (const float*)d_in[2];
    const float* c1b      = (const float*)d_in[3];
    const float* c2w      = (const float*)d_in[4];
    const float* c2b      = (const float*)d_in[5];
    const float* pw       = (const float*)d_in[6];
    const float* pb       = (const float*)d_in[7];
    float* out = (float*)d_out;
    float* out_fused  = out + OFF_FUSED;
    float* out_coords = out + OFF_COORDS;
    float* out_vf     = out + OFF_VF;

    float *p_sums, *p_tmp, *p_h, *p_p;
    float *p_s1s, *p_s1q, *p_s2s, *p_s2q;
    cudaGetSymbolAddress((void**)&p_sums, g_sums);
    cudaGetSymbolAddress((void**)&p_tmp,  g_tmp);
    cudaGetSymbolAddress((void**)&p_h,    g_h);
    cudaGetSymbolAddress((void**)&p_p,    g_p);
    cudaGetSymbolAddress((void**)&p_s1s,  g_st1s);
    cudaGetSymbolAddress((void**)&p_s1q,  g_st1q);
    cudaGetSymbolAddress((void**)&p_s2s,  g_st2s);
    cudaGetSymbolAddress((void**)&p_s2q,  g_st2q);

    cudaFuncSetAttribute(conv3d_kernel,
                         cudaFuncAttributeMaxDynamicSharedMemorySize, CONV_SMEM_BYTES);

    zero_kernel<<<8192, 256>>>();
    mean_kernel<<<BATCH, 256>>>(coords);
    maxnorm_kernel<<<BATCH, 256>>>(coords);
    voxscatter_kernel<<<BATCH*NPTS/256, 256>>>(coords, features);
    avg_kernel<<<8192, 256>>>();

    conv3d_kernel<<<BATCH*32*2, 512, CONV_SMEM_BYTES>>>(p_sums, c1w, c1b, p_tmp, p_s1s, p_s1q);
    instnorm_apply_kernel<<<BATCH*CH, 256>>>(p_tmp, p_h, p_s1s, p_s1q);
    conv3d_kernel<<<BATCH*32*2, 512, CONV_SMEM_BYTES>>>(p_h, c2w, c2b, p_tmp, p_s2s, p_s2q);
    instnorm_apply_kernel<<<BATCH*CH, 256>>>(p_tmp, out_vf, p_s2s, p_s2q);

    transpose_kernel<<<dim3(1024, 2, BATCH), 256>>>(out_vf);

    pointmlp_kernel<<<BATCH*128, 256>>>(features, pw, pb);
    instnorm_kernel<<<BATCH*CH, 256>>>(p_p, p_p);

    devox_kernel<<<BATCH*NPTS/8, 256>>>();
    final_kernel<<<BATCH*1024, 256>>>(p_p, out_fused);

    cudaMemcpyAsync(out_coords, coords, (size_t)BATCH*3*NPTS*sizeof(float),
                    cudaMemcpyDeviceToDevice);
}

// round 3
// speedup vs baseline: 2.3734x; 2.2039x over previous
#include <cuda_runtime.h>
#include <cuda_bf16.h>
#include <cstddef>
#include <cstdint>

// ---------------------------------------------------------------------------
// Problem constants
// ---------------------------------------------------------------------------
#define BATCH   8
#define CH      64
#define NPTS    32768
#define RES     32
#define RCUBE   32768
#define GRID_ELEMS (BATCH*CH*RCUBE)   // 16,777,216
#define LEAK    0.1f
#define NORM_EPS 1e-4f

#define OFF_FUSED   0
#define OFF_COORDS  (BATCH*CH*NPTS)
#define OFF_VF      (OFF_COORDS + BATCH*3*NPTS)

// ---------------------------------------------------------------------------
// Scratch
// ---------------------------------------------------------------------------
__device__ float g_sums[GRID_ELEMS];
__device__ float g_cnt [BATCH*RCUBE];
__device__ float g_tmp [GRID_ELEMS];
__device__ float g_h   [GRID_ELEMS];
__device__ float g_p   [GRID_ELEMS];
__device__ float g_vft [GRID_ELEMS];
__device__ float g_dv  [GRID_ELEMS];
__device__ float g_nc  [BATCH*3*NPTS];
__device__ float g_mean[BATCH*3];
__device__ float g_denom[BATCH];
__device__ float g_st1s[BATCH*CH];
__device__ float g_st1q[BATCH*CH];
__device__ float g_st2s[BATCH*CH];
__device__ float g_st2q[BATCH*CH];

// bf16-split staging: input grid channel-last [b][vox][64c], weights [27][co][ci]
__device__ __align__(16) __nv_bfloat16 g_ahi[GRID_ELEMS];
__device__ __align__(16) __nv_bfloat16 g_alo[GRID_ELEMS];
__device__ __align__(16) __nv_bfloat16 g_w1h[27*64*64];
__device__ __align__(16) __nv_bfloat16 g_w1l[27*64*64];
__device__ __align__(16) __nv_bfloat16 g_w2h[27*64*64];
__device__ __align__(16) __nv_bfloat16 g_w2l[27*64*64];

// ---------------------------------------------------------------------------
// mma.m16n8k16 bf16 -> fp32
// ---------------------------------------------------------------------------
__device__ __forceinline__ void mma_bf16(float* d, const uint32_t* a,
                                         uint32_t b0, uint32_t b1) {
    asm volatile(
        "mma.sync.aligned.m16n8k16.row.col.f32.bf16.bf16.f32 "
        "{%0,%1,%2,%3}, {%4,%5,%6,%7}, {%8,%9}, {%0,%1,%2,%3};"
        : "+f"(d[0]), "+f"(d[1]), "+f"(d[2]), "+f"(d[3])
        : "r"(a[0]), "r"(a[1]), "r"(a[2]), "r"(a[3]), "r"(b0), "r"(b1));
}

// ---------------------------------------------------------------------------
// 0. zero scratch
// ---------------------------------------------------------------------------
__global__ void zero_kernel() {
    int total = GRID_ELEMS + BATCH*RCUBE;
    for (int i = blockIdx.x*blockDim.x + threadIdx.x; i < total; i += gridDim.x*blockDim.x) {
        if (i < GRID_ELEMS) g_sums[i] = 0.f;
        else                g_cnt[i - GRID_ELEMS] = 0.f;
    }
    int t = blockIdx.x*blockDim.x + threadIdx.x;
    if (t < BATCH*CH) {
        g_st1s[t] = 0.f; g_st1q[t] = 0.f;
        g_st2s[t] = 0.f; g_st2q[t] = 0.f;
    }
}

// ---------------------------------------------------------------------------
// 1. per-batch coordinate mean
// ---------------------------------------------------------------------------
__global__ void mean_kernel(const float* __restrict__ coords) {
    int b = blockIdx.x, tid = threadIdx.x;
    const float* cb = coords + (size_t)b*3*NPTS;
    float s0 = 0.f, s1 = 0.f, s2 = 0.f;
    for (int n = tid; n < NPTS; n += 256) {
        s0 += cb[n]; s1 += cb[NPTS + n]; s2 += cb[2*NPTS + n];
    }
    for (int o = 16; o; o >>= 1) {
        s0 += __shfl_xor_sync(0xffffffffu, s0, o);
        s1 += __shfl_xor_sync(0xffffffffu, s1, o);
        s2 += __shfl_xor_sync(0xffffffffu, s2, o);
    }
    __shared__ float sh[3][8];
    int w = tid >> 5;
    if ((tid & 31) == 0) { sh[0][w] = s0; sh[1][w] = s1; sh[2][w] = s2; }
    __syncthreads();
    if (tid == 0) {
        float t0 = 0.f, t1 = 0.f, t2 = 0.f;
        for (int i = 0; i < 8; i++) { t0 += sh[0][i]; t1 += sh[1][i]; t2 += sh[2][i]; }
        g_mean[b*3+0] = t0 / (float)NPTS;
        g_mean[b*3+1] = t1 / (float)NPTS;
        g_mean[b*3+2] = t2 / (float)NPTS;
    }
}

// ---------------------------------------------------------------------------
// 2. per-batch max point norm
// ---------------------------------------------------------------------------
__global__ void maxnorm_kernel(const float* __restrict__ coords) {
    int b = blockIdx.x, tid = threadIdx.x;
    const float* cb = coords + (size_t)b*3*NPTS;
    float m0 = g_mean[b*3+0], m1 = g_mean[b*3+1], m2 = g_mean[b*3+2];
    float mx = 0.f;
    for (int n = tid; n < NPTS; n += 256) {
        float dx = cb[n] - m0, dy = cb[NPTS+n] - m1, dz = cb[2*NPTS+n] - m2;
        float sq = dx*dx + dy*dy + dz*dz;
        mx = fmaxf(mx, sq);
    }
    for (int o = 16; o; o >>= 1) mx = fmaxf(mx, __shfl_xor_sync(0xffffffffu, mx, o));
    __shared__ float sh[8];
    int w = tid >> 5;
    if ((tid & 31) == 0) sh[w] = mx;
    __syncthreads();
    if (tid == 0) {
        float t = 0.f;
        for (int i = 0; i < 8; i++) t = fmaxf(t, sh[i]);
        g_denom[b] = 2.0f * sqrtf(t);
    }
}

// ---------------------------------------------------------------------------
// 3. norm_coords + scatter-add
// ---------------------------------------------------------------------------
__global__ void voxscatter_kernel(const float* __restrict__ coords,
                                  const float* __restrict__ features) {
    int t = blockIdx.x*blockDim.x + threadIdx.x;
    int b = t >> 15, n = t & (NPTS-1);
    float den = g_denom[b];
    int vi[3];
#pragma unroll
    for (int d = 0; d < 3; d++) {
        float c = coords[((size_t)b*3 + d)*NPTS + n];
        float v = (c - g_mean[b*3+d]) / den + 0.5f;
        v *= (float)RES;
        v = fminf(fmaxf(v, 0.f), (float)(RES-1));
        g_nc[((size_t)b*3 + d)*NPTS + n] = v;
        vi[d] = (int)rintf(v);
    }
    int vox = vi[0]*RES*RES + vi[1]*RES + vi[2];
    atomicAdd(&g_cnt[b*RCUBE + vox], 1.f);
    size_t fb = (size_t)b*CH*NPTS + n;
    size_t sb = (size_t)b*CH*RCUBE + vox;
#pragma unroll 4
    for (int c = 0; c < CH; c++)
        atomicAdd(&g_sums[sb + (size_t)c*RCUBE], features[fb + (size_t)c*NPTS]);
}

// ---------------------------------------------------------------------------
// 4. average
// ---------------------------------------------------------------------------
__global__ void avg_kernel() {
    for (int i = blockIdx.x*blockDim.x + threadIdx.x; i < GRID_ELEMS; i += gridDim.x*blockDim.x) {
        int b   = i >> 21;
        int vox = i & (RCUBE-1);
        g_sums[i] = g_sums[i] / fmaxf(g_cnt[b*RCUBE + vox], 1.f);
    }
}

// ---------------------------------------------------------------------------
// 5a. weight prep: W[co][ci][27] fp32 -> hi/lo bf16 [27][co][ci]
// ---------------------------------------------------------------------------
__global__ void wprep_kernel(const float* __restrict__ W,
                             __nv_bfloat16* __restrict__ hi,
                             __nv_bfloat16* __restrict__ lo) {
    int i = blockIdx.x*256 + threadIdx.x;        // over 27*64*64 = 110592
    if (i >= 27*64*64) return;
    int ci = i & 63;
    int rest = i >> 6;
    int co = rest & 63, off = rest >> 6;
    float v = W[((size_t)co*64 + ci)*27 + off];
    __nv_bfloat16 h = __float2bfloat16(v);
    hi[i] = h;
    lo[i] = __float2bfloat16(v - __bfloat162float(h));
}

// ---------------------------------------------------------------------------
// 5b. input prep: [b][c][vox] fp32 -> channel-last hi/lo bf16 [b][vox][64]
// ---------------------------------------------------------------------------
__global__ void aprep_kernel(const float* __restrict__ src) {
    __shared__ float t[32][33];
    int b = blockIdx.z, ct = blockIdx.y, vt = blockIdx.x;
    int tx = threadIdx.x & 31, ty = threadIdx.x >> 5;     // 32x8
    const float* s = src + ((size_t)b*CH + ct*32)*RCUBE + vt*32;
#pragma unroll
    for (int k = 0; k < 32; k += 8) t[ty+k][tx] = s[(size_t)(ty+k)*RCUBE + tx];
    __syncthreads();
#pragma unroll
    for (int k = 0; k < 32; k += 8) {
        float v = t[tx][ty+k];
        __nv_bfloat16 h = __float2bfloat16(v);
        size_t di = ((size_t)b*RCUBE + vt*32 + ty + k)*CH + ct*32 + tx;
        g_ahi[di] = h;
        g_alo[di] = __float2bfloat16(v - __bfloat162float(h));
    }
}

// ---------------------------------------------------------------------------
// 5c. Conv3d 3x3x3 SAME via bf16-split tensor-core implicit GEMM.
//     CTA = (b, d, h-half). 256 thr = 8 warps; warp tile M=64 (spatial), N=64 co.
//     K loop: 4 ci16 chunks x 27 offsets x 3 split passes.
// ---------------------------------------------------------------------------
#define SA_BF16 (3*18*34*16)      // 29376 (pos-major, 16 ci contiguous)
#define SWT_BF16 (27*64*16)       // 27648 ([off][co][ci16])
#define CONV_SMEM ((2*SA_BF16 + 2*SWT_BF16)*2)   // 228,096 bytes

__global__ __launch_bounds__(256, 1)
void conv_mma_kernel(const __nv_bfloat16* __restrict__ Whi,
                     const __nv_bfloat16* __restrict__ Wlo,
                     const float* __restrict__ bias,
                     float* __restrict__ out,
                     float* __restrict__ ss, float* __restrict__ sq) {
    extern __shared__ __align__(16) char smem_raw[];
    __nv_bfloat16* sAh = (__nv_bfloat16*)smem_raw;
    __nv_bfloat16* sAl = sAh + SA_BF16;
    __nv_bfloat16* sWh = sAl + SA_BF16;
    __nv_bfloat16* sWl = sWh + SWT_BF16;

    int bid = blockIdx.x;
    int hh = bid & 1, d = (bid >> 1) & 31, b = bid >> 6;
    int h0 = hh * 16;
    int tid = threadIdx.x;
    int warp = tid >> 5, lane = tid & 31;
    int g = lane >> 2, tg = lane & 3;

    float acc[4][8][4];
#pragma unroll
    for (int t = 0; t < 4; t++)
#pragma unroll
        for (int n = 0; n < 8; n++)
#pragma unroll
            for (int e = 0; e < 4; e++) acc[t][n][e] = 0.f;

    // per-thread A fragment base byte offsets (pos*32 + tg*4)
    int abase[4];
#pragma unroll
    for (int t = 0; t < 4; t++) {
        int h_loc = warp*2 + (t >> 1);
        int wb = (t & 1)*16;
        abase[t] = (h_loc*34 + wb + g)*32 + tg*4;
    }
    int bthread = g*32 + tg*4;

    for (int ci0 = 0; ci0 < 64; ci0 += 16) {
        // --- load A slab (hi+lo), zero halo ---
        for (int u = tid; u < 2*3*18*34; u += 256) {
            int halfsel = u & 1, pos = u >> 1;
            int dd = pos / 612;
            int r  = pos - dd*612;
            int hy = r / 34;
            int ww = r - hy*34;
            int gd = d - 1 + dd, gh = h0 - 1 + hy, gw = ww - 1;
            uint4 vh = make_uint4(0,0,0,0), vl = make_uint4(0,0,0,0);
            if ((unsigned)gd < 32u && (unsigned)gh < 32u && (unsigned)gw < 32u) {
                size_t gi = ((size_t)b*RCUBE + gd*1024 + gh*32 + gw)*64 + ci0 + halfsel*8;
                vh = *(const uint4*)(g_ahi + gi);
                vl = *(const uint4*)(g_alo + gi);
            }
            ((uint4*)sAh)[u] = vh;
            ((uint4*)sAl)[u] = vl;
        }
        // --- load W chunk ---
        for (int u = tid; u < 2*27*64; u += 256) {
            int halfsel = u & 1, row = u >> 1;
            size_t gi = (size_t)row*64 + ci0 + halfsel*8;
            ((uint4*)sWh)[u] = *(const uint4*)(Whi + gi);
            ((uint4*)sWl)[u] = *(const uint4*)(Wlo + gi);
        }
        __syncthreads();

        int dd = 0, dh = 0, dw = 0;
#pragma unroll 1
        for (int off = 0; off < 27; ++off) {
            int rowoff = ((dd*18 + dh)*34 + dw)*32;   // bytes
            uint32_t ah[4][4], al[4][4];
#pragma unroll
            for (int t = 0; t < 4; ++t) {
                const char* pa = (const char*)sAh + rowoff + abase[t];
                const char* pl = (const char*)sAl + rowoff + abase[t];
                ah[t][0] = *(const uint32_t*)(pa);
                ah[t][2] = *(const uint32_t*)(pa + 16);
                ah[t][1] = *(const uint32_t*)(pa + 256);
                ah[t][3] = *(const uint32_t*)(pa + 272);
                al[t][0] = *(const uint32_t*)(pl);
                al[t][2] = *(const uint32_t*)(pl + 16);
                al[t][1] = *(const uint32_t*)(pl + 256);
                al[t][3] = *(const uint32_t*)(pl + 272);
            }
            int bo = off*2048 + bthread;              // bytes
#pragma unroll
            for (int n8 = 0; n8 < 8; ++n8) {
                const char* pbh = (const char*)sWh + bo + n8*256;
                const char* pbl = (const char*)sWl + bo + n8*256;
                uint32_t bh0 = *(const uint32_t*)(pbh);
                uint32_t bh1 = *(const uint32_t*)(pbh + 16);
                uint32_t bl0 = *(const uint32_t*)(pbl);
                uint32_t bl1 = *(const uint32_t*)(pbl + 16);
#pragma unroll
                for (int t = 0; t < 4; ++t) {
                    mma_bf16(acc[t][n8], ah[t], bh0, bh1);   // hi*hi
                    mma_bf16(acc[t][n8], al[t], bh0, bh1);   // lo*hi
                    mma_bf16(acc[t][n8], ah[t], bl0, bl1);   // hi*lo
                }
            }
            if (++dw == 3) { dw = 0; if (++dh == 3) { dh = 0; ++dd; } }
        }
        __syncthreads();
    }

    // --- epilogue: bias, store, fused IN stats ---
#pragma unroll
    for (int n8 = 0; n8 < 8; ++n8) {
#pragma unroll
        for (int par = 0; par < 2; ++par) {
            int co = n8*8 + 2*tg + par;
            float bb = __ldg(&bias[co]);
            float s = 0.f, q = 0.f;
            size_t obase = ((size_t)b*CH + co)*RCUBE + d*1024;
#pragma unroll
            for (int t = 0; t < 4; ++t) {
                int h_loc = warp*2 + (t >> 1);
                int wb = (t & 1)*16;
#pragma unroll
                for (int rh = 0; rh < 2; ++rh) {
                    float v = acc[t][n8][rh*2 + par] + bb;
                    out[obase + (h0 + h_loc)*32 + wb + g + rh*8] = v;
                    s += v;
                    q = fmaf(v, v, q);
                }
            }
            s += __shfl_xor_sync(0xffffffffu, s, 4);
            q += __shfl_xor_sync(0xffffffffu, q, 4);
            s += __shfl_xor_sync(0xffffffffu, s, 8);
            q += __shfl_xor_sync(0xffffffffu, q, 8);
            s += __shfl_xor_sync(0xffffffffu, s, 16);
            q += __shfl_xor_sync(0xffffffffu, q, 16);
            if (g == 0) {
                atomicAdd(&ss[b*CH + co], s);
                atomicAdd(&sq[b*CH + co], q);
            }
        }
    }
}

// ---------------------------------------------------------------------------
// 6a. InstanceNorm apply (+leaky) from precomputed stats
// ---------------------------------------------------------------------------
__global__ void instnorm_apply_kernel(const float* __restrict__ in, float* __restrict__ out,
                                      const float* __restrict__ ss, const float* __restrict__ sq) {
    int gidx = blockIdx.x, tid = threadIdx.x;
    float m   = ss[gidx] / (float)RCUBE;
    float var = fmaxf(sq[gidx] / (float)RCUBE - m*m, 0.f);
    float rs  = rsqrtf(var + NORM_EPS);
    const float* x = in + (size_t)gidx*RCUBE;
    float* y = out + (size_t)gidx*RCUBE;
    for (int i = tid; i < RCUBE; i += 256) {
        float v = (x[i] - m) * rs;
        y[i] = (v >= 0.f) ? v : LEAK * v;
    }
}

// ---------------------------------------------------------------------------
// 6b. full InstanceNorm (+leaky) — point branch
// ---------------------------------------------------------------------------
__global__ void instnorm_kernel(const float* __restrict__ in, float* __restrict__ out) {
    int gidx = blockIdx.x, tid = threadIdx.x;
    const float* x = in + (size_t)gidx*RCUBE;
    float s = 0.f, s2 = 0.f;
    for (int i = tid; i < RCUBE; i += 256) {
        float v = x[i];
        s += v;
        s2 = fmaf(v, v, s2);
    }
    for (int o = 16; o; o >>= 1) {
        s  += __shfl_xor_sync(0xffffffffu, s,  o);
        s2 += __shfl_xor_sync(0xffffffffu, s2, o);
    }
    __shared__ float shs[8], shs2[8];
    __shared__ float smean, srstd;
    int w = tid >> 5;
    if ((tid & 31) == 0) { shs[w] = s; shs2[w] = s2; }
    __syncthreads();
    if (tid == 0) {
        float a = 0.f, b2 = 0.f;
        for (int i = 0; i < 8; i++) { a += shs[i]; b2 += shs2[i]; }
        float m   = a / (float)RCUBE;
        float var = fmaxf(b2 / (float)RCUBE - m*m, 0.f);
        smean = m;
        srstd = rsqrtf(var + NORM_EPS);
    }
    __syncthreads();
    float m = smean, rs = srstd;
    float* y = out + (size_t)gidx*RCUBE;
    for (int i = tid; i < RCUBE; i += 256) {
        float v = (x[i] - m) * rs;
        y[i] = (v >= 0.f) ? v : LEAK * v;
    }
}

// ---------------------------------------------------------------------------
// 7. transpose voxel features [b][c][vox] -> [b][vox][c]
// ---------------------------------------------------------------------------
__global__ void transpose_kernel(const float* __restrict__ vf) {
    __shared__ float t[32][33];
    int b = blockIdx.z, ct = blockIdx.y, vt = blockIdx.x;
    int tx = threadIdx.x & 31, ty = threadIdx.x >> 5;
    const float* src = vf + ((size_t)b*CH + ct*32)*RCUBE + vt*32;
#pragma unroll
    for (int k = 0; k < 32; k += 8) t[ty+k][tx] = src[(size_t)(ty+k)*RCUBE + tx];
    __syncthreads();
    float* dst = g_vft + ((size_t)b*RCUBE + vt*32)*CH + ct*32;
#pragma unroll
    for (int k = 0; k < 32; k += 8) dst[(size_t)(ty+k)*CH + tx] = t[tx][ty+k];
}

// ---------------------------------------------------------------------------
// 8. point branch GEMM
// ---------------------------------------------------------------------------
__global__ void pointmlp_kernel(const float* __restrict__ features,
                                const float* __restrict__ pw,
                                const float* __restrict__ pb) {
    __shared__ float sw[64*64];
    __shared__ float sb[64];
    int tid = threadIdx.x;
    for (int i = tid; i < 4096; i += 256) sw[i] = pw[i];
    if (tid < 64) sb[tid] = pb[tid];
    __syncthreads();
    int blk = blockIdx.x;
    int b = blk >> 7;
    int n = (blk & 127)*256 + tid;
    float acc[64];
#pragma unroll
    for (int o = 0; o < 64; o++) acc[o] = 0.f;
    const float* f = features + (size_t)b*CH*NPTS + n;
    for (int c = 0; c < 64; c++) {
        float v = f[(size_t)c*NPTS];
#pragma unroll
        for (int o = 0; o < 64; o++) acc[o] = fmaf(sw[o*64 + c], v, acc[o]);
    }
    float* p = g_p + (size_t)b*CH*NPTS + n;
#pragma unroll
    for (int o = 0; o < 64; o++) p[(size_t)o*NPTS] = acc[o] + sb[o];
}

// ---------------------------------------------------------------------------
// 9. trilinear devoxelize
// ---------------------------------------------------------------------------
__global__ void devox_kernel() {
    int tid = threadIdx.x;
    int warp = tid >> 5, lane = tid & 31;
    int pidx = blockIdx.x*8 + warp;
    int b = pidx >> 15, n = pidx & (NPTS-1);
    float nx = g_nc[((size_t)b*3 + 0)*NPTS + n];
    float ny = g_nc[((size_t)b*3 + 1)*NPTS + n];
    float nz = g_nc[((size_t)b*3 + 2)*NPTS + n];
    int lx = (int)floorf(nx), ly = (int)floorf(ny), lz = (int)floorf(nz);
    float fx = nx - (float)lx, fy = ny - (float)ly, fz = nz - (float)lz;
    int hx = min(lx+1, 31), hy = min(ly+1, 31), hz = min(lz+1, 31);
    const float* base = g_vft + (size_t)b*RCUBE*CH;
    float a0 = 0.f, a1 = 0.f;
#pragma unroll
    for (int k = 0; k < 8; k++) {
        int dx = k >> 2, dy = (k >> 1) & 1, dz = k & 1;
        int ix = dx ? hx : lx, iy = dy ? hy : ly, iz = dz ? hz : lz;
        float wgt = (dx ? fx : 1.f-fx) * (dy ? fy : 1.f-fy) * (dz ? fz : 1.f-fz);
        const float* p = base + (size_t)(ix*1024 + iy*32 + iz)*CH;
        a0 = fmaf(wgt, p[lane],      a0);
        a1 = fmaf(wgt, p[lane + 32], a1);
    }
    float* d = g_dv + ((size_t)b*NPTS + n)*CH;
    d[lane]      = a0;
    d[lane + 32] = a1;
}

// ---------------------------------------------------------------------------
// 10. final fuse
// ---------------------------------------------------------------------------
__global__ void final_kernel(const float* __restrict__ pn, float* __restrict__ outf) {
    __shared__ float t[32][65];
    int blk = blockIdx.x;
    int b = blk >> 10;
    int n0 = (blk & 1023)*32;
    int tid = threadIdx.x;
    const float* dvb = g_dv + ((size_t)b*NPTS + n0)*CH;
    for (int i = tid; i < 2048; i += 256) {
        int c = i & 63, nl = i >> 6;
        t[nl][c] = dvb[(size_t)nl*CH + c];
    }
    __syncthreads();
    size_t ob = (size_t)b*CH*NPTS + n0;
    for (int i = tid; i < 2048; i += 256) {
        int nl = i & 31, c = i >> 5;
        size_t o = ob + (size_t)c*NPTS + nl;
        outf[o] = t[nl][c] + pn[o];
    }
}

// ---------------------------------------------------------------------------
// launch
// ---------------------------------------------------------------------------
extern "C" void kernel_launch(void* const* d_in, const int* in_sizes, int n_in,
                              void* d_out, int out_size) {
    const float* features = (const float*)d_in[0];
    const float* coords   = (const float*)d_in[1];
    const float* c1w      = (const float*)d_in[2];
    const float* c1b      = (const float*)d_in[3];
    const float* c2w      = (const float*)d_in[4];
    const float* c2b      = (const float*)d_in[5];
    const float* pw       = (const float*)d_in[6];
    const float* pb       = (const float*)d_in[7];
    float* out = (float*)d_out;
    float* out_fused  = out + OFF_FUSED;
    float* out_coords = out + OFF_COORDS;
    float* out_vf     = out + OFF_VF;

    float *p_sums, *p_tmp, *p_h, *p_p;
    float *p_s1s, *p_s1q, *p_s2s, *p_s2q;
    __nv_bfloat16 *p_w1h, *p_w1l, *p_w2h, *p_w2l;
    cudaGetSymbolAddress((void**)&p_sums, g_sums);
    cudaGetSymbolAddress((void**)&p_tmp,  g_tmp);
    cudaGetSymbolAddress((void**)&p_h,    g_h);
    cudaGetSymbolAddress((void**)&p_p,    g_p);
    cudaGetSymbolAddress((void**)&p_s1s,  g_st1s);
    cudaGetSymbolAddress((void**)&p_s1q,  g_st1q);
    cudaGetSymbolAddress((void**)&p_s2s,  g_st2s);
    cudaGetSymbolAddress((void**)&p_s2q,  g_st2q);
    cudaGetSymbolAddress((void**)&p_w1h,  g_w1h);
    cudaGetSymbolAddress((void**)&p_w1l,  g_w1l);
    cudaGetSymbolAddress((void**)&p_w2h,  g_w2h);
    cudaGetSymbolAddress((void**)&p_w2l,  g_w2l);

    cudaFuncSetAttribute(conv_mma_kernel,
                         cudaFuncAttributeMaxDynamicSharedMemorySize, CONV_SMEM);

    zero_kernel<<<8192, 256>>>();
    mean_kernel<<<BATCH, 256>>>(coords);
    maxnorm_kernel<<<BATCH, 256>>>(coords);
    voxscatter_kernel<<<BATCH*NPTS/256, 256>>>(coords, features);
    avg_kernel<<<8192, 256>>>();

    wprep_kernel<<<(27*64*64 + 255)/256, 256>>>(c1w, p_w1h, p_w1l);
    wprep_kernel<<<(27*64*64 + 255)/256, 256>>>(c2w, p_w2h, p_w2l);

    // conv1
    aprep_kernel<<<dim3(1024, 2, BATCH), 256>>>(p_sums);
    conv_mma_kernel<<<BATCH*32*2, 256, CONV_SMEM>>>(p_w1h, p_w1l, c1b, p_tmp, p_s1s, p_s1q);
    instnorm_apply_kernel<<<BATCH*CH, 256>>>(p_tmp, p_h, p_s1s, p_s1q);
    // conv2
    aprep_kernel<<<dim3(1024, 2, BATCH), 256>>>(p_h);
    conv_mma_kernel<<<BATCH*32*2, 256, CONV_SMEM>>>(p_w2h, p_w2l, c2b, p_tmp, p_s2s, p_s2q);
    instnorm_apply_kernel<<<BATCH*CH, 256>>>(p_tmp, out_vf, p_s2s, p_s2q);

    transpose_kernel<<<dim3(1024, 2, BATCH), 256>>>(out_vf);

    pointmlp_kernel<<<BATCH*128, 256>>>(features, pw, pb);
    instnorm_kernel<<<BATCH*CH, 256>>>(p_p, p_p);

    devox_kernel<<<BATCH*NPTS/8, 256>>>();
    final_kernel<<<BATCH*1024, 256>>>(p_p, out_fused);

    cudaMemcpyAsync(out_coords, coords, (size_t)BATCH*3*NPTS*sizeof(float),
                    cudaMemcpyDeviceToDevice);
}